// round 15
// baseline (speedup 1.0000x reference)
#include <cuda_runtime.h>
#include <cuda_bf16.h>
#include <math.h>

// AssociativeLIF forward: T=8, B=128, D=8192, NC=64
// d_out = [ ss (T,B,D) | vt (T,B,D) ] float32
// One CTA per batch row. Thread owns d = 4*tid + j and d = 4096 + 4*tid + j, j=0..3.
// Fast path (cids[d] == d%64): thread's 8 neurons hit clusters 4*(tid&15)+j.
// Counts: bit->byte pack, shfl16 fold, pair-fold, 8x 64-bit smem atomics per warp.
// Cascade dot: thread (c=tid>>4, g=tid&15), shfl-butterfly reduce, 2 barriers/step.

#define T_STEPS 8
#define BATCH   128
#define DIM     8192
#define NC      64
#define TPB     1024
#define V_RESET (-0.1f)

__global__ __launch_bounds__(TPB, 1)
void assoc_lif_kernel(const float* __restrict__ x,        // [T,B,D]
                      const float* __restrict__ th_raw,   // [D]
                      const float* __restrict__ bm_raw,   // [1]
                      const float* __restrict__ bs_raw,   // [1]
                      const float* __restrict__ nw,       // [NC,NC]
                      const float* __restrict__ gain,     // [NC]
                      const int*   __restrict__ cids,     // [D]
                      float* __restrict__ out_s,          // [T,B,D]
                      float* __restrict__ out_v)          // [T,B,D]
{
    // W2[c*64 + j] = sigmoid(nw[c][j]) / 128  (identity layout; /128 exact)
    __shared__ __align__(16) float              W2[NC * NC];
    __shared__ float                            g_sm[NC];
    __shared__ __align__(16) unsigned long long cnt64[2][8];   // 16 packed-byte words as 8 u64
    __shared__ __align__(16) float              cf_slow[2][NC];
    __shared__ __align__(16) float              ns[NC];
    __shared__ float bm_sh, bs_sh;

    const int b   = blockIdx.x;
    const int tid = threadIdx.x;

    // ---- one-time parameter prep ----
    for (int idx = tid; idx < NC * NC; idx += TPB)
        W2[idx] = (1.0f / (1.0f + expf(-nw[idx]))) * (1.0f / 128.0f);
    if (tid < NC)      g_sm[tid] = gain[tid];
    if (tid < 16)      ((unsigned long long*)cnt64)[tid] = 0ull;
    if (tid < 2 * NC)  ((float*)cf_slow)[tid] = 0.0f;
    if (tid == 0) {
        float bm = 1.0f / (1.0f + expf(-bm_raw[0]));
        bm_sh = fminf(fmaxf(bm, 0.8f), 0.98f);
        bs_sh = 1.0f / (1.0f + expf(-bs_raw[0]));
    }

    // fast path iff cids[d] == d % 64 for this thread's 8 neurons
    bool okf = true;
    #pragma unroll
    for (int j = 0; j < 4; j++) {
        okf &= (cids[4 * tid + j]        == ((4 * tid + j) & 63));
        okf &= (cids[4 * tid + 4096 + j] == ((4 * tid + j) & 63));
    }
    const bool fast = (__syncthreads_and((int)okf) != 0);   // also fences smem init

    const float bm = bm_sh, bs = bs_sh, om = 1.0f - bm;

    const size_t bd4   = (size_t)b * DIM / 4;
    const size_t step4 = (size_t)BATCH * DIM / 4;

    const float4* xp = (const float4*)x + bd4 + tid;
    float4*       sp = (float4*)out_s   + bd4 + tid;
    float4*       vp = (float4*)out_v   + bd4 + tid;

    // ---- per-thread state ----
    float v[8], isyn[8], th[8], xv[8];
    unsigned sm1 = 0, sm2 = 0;          // spike masks at t-1, t-2 (refractory)
    {
        const float4* t4 = (const float4*)th_raw + tid;
        float4 t0 = t4[0], t1 = t4[1024];
        th[0]=t0.x; th[1]=t0.y; th[2]=t0.z; th[3]=t0.w;
        th[4]=t1.x; th[5]=t1.y; th[6]=t1.z; th[7]=t1.w;
        #pragma unroll
        for (int k = 0; k < 8; k++) {
            th[k] = fminf(fmaxf(th[k], 0.05f), 0.5f);
            v[k] = 0.0f; isyn[k] = 0.0f;
        }
        float4 a = xp[0], c = xp[1024];     // preload t=0
        xv[0]=a.x; xv[1]=a.y; xv[2]=a.z; xv[3]=a.w;
        xv[4]=c.x; xv[5]=c.y; xv[6]=c.z; xv[7]=c.w;
    }

    #pragma unroll
    for (int t = 0; t < T_STEPS; t++) {
        const int buf = t & 1;
        const bool need_cascade = (t + 1 < T_STEPS);   // i_syn dead after last step

        // ---- LIF update + spike (refrac>0 <=> spiked at t-1 or t-2) ----
        const unsigned refr = sm1 | sm2;
        unsigned smask = 0;
        #pragma unroll
        for (int k = 0; k < 8; k++) {
            isyn[k] = fmaf(bs, isyn[k], xv[k]);
            float nv = fmaf(bm, v[k], om * isyn[k]);
            v[k] = ((refr >> k) & 1u) ? V_RESET : nv;
            if (v[k] >= th[k]) smask |= (1u << k);
        }
        sm2 = sm1; sm1 = smask;

        // ---- spike counting: pack, fold 32->16->8 lanes, 64-bit atomics ----
        if (need_cascade) {
            if (fast) {
                unsigned m0 = smask & 0xFu, m1 = (smask >> 4) & 0xFu;
                unsigned packed = ((m0 * 0x00204081u) & 0x01010101u)
                                + ((m1 * 0x00204081u) & 0x01010101u);
                packed += __shfl_xor_sync(0xFFFFFFFFu, packed, 16);
                unsigned other = __shfl_xor_sync(0xFFFFFFFFu, packed, 1);
                const int lane = tid & 31;
                if (lane < 16 && !(lane & 1)) {
                    // even lane m holds words m (lo) and m+1 (hi); bytes <=128, no carry
                    unsigned long long u = (unsigned long long)packed
                                         | ((unsigned long long)other << 32);
                    if (u) atomicAdd(&cnt64[buf][lane >> 1], u);
                }
            } else {
                #pragma unroll
                for (int k = 0; k < 8; k++)
                    if (smask & (1u << k)) {
                        int d = 4 * tid + (k & 3) + (k >> 2) * 4096;
                        atomicAdd(&cf_slow[buf][__ldg(&cids[d])], 1.0f);   // exact, order-free
                    }
            }

            // ---- prefetch next x (register double-buffer; long load->use distance) ----
            const float4* xn = xp + (size_t)(t + 1) * step4;
            float4 a = __ldg(xn), c = __ldg(xn + 1024);
            xv[0]=a.x; xv[1]=a.y; xv[2]=a.z; xv[3]=a.w;
            xv[4]=c.x; xv[5]=c.y; xv[6]=c.z; xv[7]=c.w;
        }

        // ---- reset + streaming stores (independent of cascade result) ----
        {
            float sv[8];
            #pragma unroll
            for (int k = 0; k < 8; k++) {
                float sk = (smask >> k) & 1u ? 1.0f : 0.0f;
                sv[k] = sk;
                v[k] = fmaf(-sk, th[k], v[k]);
            }
            float4* st = sp + (size_t)t * step4;
            float4* vt = vp + (size_t)t * step4;
            __stcs(st,        make_float4(sv[0], sv[1], sv[2], sv[3]));
            __stcs(st + 1024, make_float4(sv[4], sv[5], sv[6], sv[7]));
            __stcs(vt,        make_float4(v[0], v[1], v[2], v[3]));
            __stcs(vt + 1024, make_float4(v[4], v[5], v[6], v[7]));
        }

        if (!need_cascade) break;      // last step: no cascade consumer

        __syncthreads();   // counts complete (barrier drains pending atomics)

        // ---- fused dot: thread (c=tid>>4, g=tid&15), shfl-reduce over g ----
        {
            const int c = tid >> 4, g = tid & 15;
            float f0, f1, f2, f3;
            if (fast) {
                unsigned u = ((const unsigned*)cnt64[buf])[g];
                f0 = __uint_as_float(__byte_perm(u, 0x4B000000u, 0x7540)) - 8388608.0f;
                f1 = __uint_as_float(__byte_perm(u, 0x4B000000u, 0x7541)) - 8388608.0f;
                f2 = __uint_as_float(__byte_perm(u, 0x4B000000u, 0x7542)) - 8388608.0f;
                f3 = __uint_as_float(__byte_perm(u, 0x4B000000u, 0x7543)) - 8388608.0f;
            } else {
                float4 cf4 = ((const float4*)cf_slow[buf])[g];
                f0 = cf4.x; f1 = cf4.y; f2 = cf4.z; f3 = cf4.w;
            }
            // W2 row strip for (c, 4g..4g+3): one conflict-free LDS.128
            float4 w = ((const float4*)W2)[tid];
            float acc = (f0 * w.x + f1 * w.y) + (f2 * w.z + f3 * w.w);
            acc += __shfl_xor_sync(0xFFFFFFFFu, acc, 1);
            acc += __shfl_xor_sync(0xFFFFFFFFu, acc, 2);
            acc += __shfl_xor_sync(0xFFFFFFFFu, acc, 4);
            acc += __shfl_xor_sync(0xFFFFFFFFu, acc, 8);
            if (g == 0) ns[c] = acc * g_sm[c];

            if (tid < 8)  cnt64[buf ^ 1][tid] = 0ull;    // consumed two syncs ago
            if (tid < NC) cf_slow[buf ^ 1][tid] = 0.0f;
        }

        __syncthreads();   // ns ready (+ next-buf zeroing ordered before next atomics)

        // ---- apply cascade to i_syn ----
        if (fast) {
            float4 nsv = ((const float4*)ns)[tid & 15];
            isyn[0] += nsv.x; isyn[1] += nsv.y; isyn[2] += nsv.z; isyn[3] += nsv.w;
            isyn[4] += nsv.x; isyn[5] += nsv.y; isyn[6] += nsv.z; isyn[7] += nsv.w;
        } else {
            #pragma unroll
            for (int k = 0; k < 8; k++) {
                int d = 4 * tid + (k & 3) + (k >> 2) * 4096;
                isyn[k] += ns[__ldg(&cids[d])];
            }
        }
    }
}

extern "C" void kernel_launch(void* const* d_in, const int* in_sizes, int n_in,
                              void* d_out, int out_size)
{
    const float* x      = (const float*)d_in[0];   // current_in [T,B,D]
    const float* th_raw = (const float*)d_in[1];   // threshold_raw [D]
    const float* bm_raw = (const float*)d_in[2];   // beta_mem_raw
    const float* bs_raw = (const float*)d_in[3];   // beta_syn_raw
    const float* nw     = (const float*)d_in[4];   // neighbor_weights [NC,NC]
    const float* gain   = (const float*)d_in[5];   // cluster_gain [NC]
    const int*   cids   = (const int*)d_in[6];     // cluster_ids [D]

    float* out_s = (float*)d_out;
    float* out_v = out_s + (size_t)T_STEPS * BATCH * DIM;

    assoc_lif_kernel<<<BATCH, TPB>>>(x, th_raw, bm_raw, bs_raw, nw, gain, cids,
                                     out_s, out_v);
}

// round 16
// speedup vs baseline: 1.0115x; 1.0115x over previous
#include <cuda_runtime.h>
#include <cuda_bf16.h>
#include <math.h>

// AssociativeLIF forward: T=8, B=128, D=8192, NC=64
// d_out = [ ss (T,B,D) | vt (T,B,D) ] float32
// One CTA per batch row. Thread owns d = 4*tid + j and d = 4096 + 4*tid + j, j=0..3.
// Fast path (cids[d] == d%64): thread's 8 neurons hit clusters 4*(tid&15)+j.
// Counts: bit->byte pack, shfl16 fold, shfl1 pair-fold, 8x u64 smem atomics/warp.
// Cascade dot: thread (c=tid>>4, g=tid&15), shfl-butterfly reduce, 2 barriers/step.
// x input pipelined via cp.async into double-buffered smem.

#define T_STEPS 8
#define BATCH   128
#define DIM     8192
#define NC      64
#define TPB     1024
#define V_RESET (-0.1f)
#define XBUF_BYTES (2 * 2048 * 16)   // 2 buffers x 2048 float4 = 64 KB

__device__ __forceinline__ void cp_async16(void* smem_dst, const void* gmem_src) {
    unsigned s = (unsigned)__cvta_generic_to_shared(smem_dst);
    asm volatile("cp.async.cg.shared.global [%0], [%1], 16;" :: "r"(s), "l"(gmem_src) : "memory");
}
__device__ __forceinline__ void cp_commit() {
    asm volatile("cp.async.commit_group;" ::: "memory");
}
__device__ __forceinline__ void cp_wait0() {
    asm volatile("cp.async.wait_group 0;" ::: "memory");
}

__global__ __launch_bounds__(TPB, 1)
void assoc_lif_kernel(const float* __restrict__ x,        // [T,B,D]
                      const float* __restrict__ th_raw,   // [D]
                      const float* __restrict__ bm_raw,   // [1]
                      const float* __restrict__ bs_raw,   // [1]
                      const float* __restrict__ nw,       // [NC,NC]
                      const float* __restrict__ gain,     // [NC]
                      const int*   __restrict__ cids,     // [D]
                      float* __restrict__ out_s,          // [T,B,D]
                      float* __restrict__ out_v)          // [T,B,D]
{
    // W2[c*64 + j] = sigmoid(nw[c][j]) / 128  (identity layout; /128 exact)
    __shared__ __align__(16) float              W2[NC * NC];
    __shared__ float                            g_sm[NC];
    __shared__ __align__(16) unsigned long long cnt64[2][8];   // 16 packed-byte words as 8 u64
    __shared__ __align__(16) float              cf_slow[2][NC];
    __shared__ __align__(16) float              ns[NC];
    __shared__ float bm_sh, bs_sh;
    extern __shared__ __align__(16) float4 xbuf[];             // [2][2048] staging for x

    const int b   = blockIdx.x;
    const int tid = threadIdx.x;

    const size_t bd4   = (size_t)b * DIM / 4;
    const size_t step4 = (size_t)BATCH * DIM / 4;
    const float4* x4 = (const float4*)x + bd4 + tid;

    // ---- kick off x(t=0) fetch immediately ----
    cp_async16(&xbuf[tid],        x4);
    cp_async16(&xbuf[tid + 1024], x4 + 1024);
    cp_commit();

    // ---- one-time parameter prep ----
    for (int idx = tid; idx < NC * NC; idx += TPB)
        W2[idx] = (1.0f / (1.0f + expf(-nw[idx]))) * (1.0f / 128.0f);
    if (tid < NC)      g_sm[tid] = gain[tid];
    if (tid < 16)      ((unsigned long long*)cnt64)[tid] = 0ull;
    if (tid < 2 * NC)  ((float*)cf_slow)[tid] = 0.0f;
    if (tid == 0) {
        float bm = 1.0f / (1.0f + expf(-bm_raw[0]));
        bm_sh = fminf(fmaxf(bm, 0.8f), 0.98f);
        bs_sh = 1.0f / (1.0f + expf(-bs_raw[0]));
    }

    // fast path iff cids[d] == d % 64 for this thread's 8 neurons
    bool okf = true;
    #pragma unroll
    for (int j = 0; j < 4; j++) {
        okf &= (cids[4 * tid + j]        == ((4 * tid + j) & 63));
        okf &= (cids[4 * tid + 4096 + j] == ((4 * tid + j) & 63));
    }
    const bool fast = (__syncthreads_and((int)okf) != 0);   // also fences smem init

    const float bm = bm_sh, bs = bs_sh, om = 1.0f - bm;

    float4*       s4 = (float4*)out_s + bd4 + tid;
    float4*       v4 = (float4*)out_v + bd4 + tid;

    // ---- per-thread state ----
    float v[8], isyn[8], th[8];
    unsigned sm1 = 0, sm2 = 0;          // spike masks at t-1, t-2 (refractory)
    {
        const float4* t4 = (const float4*)th_raw + tid;
        float4 t0 = t4[0], t1 = t4[1024];
        th[0]=t0.x; th[1]=t0.y; th[2]=t0.z; th[3]=t0.w;
        th[4]=t1.x; th[5]=t1.y; th[6]=t1.z; th[7]=t1.w;
        #pragma unroll
        for (int k = 0; k < 8; k++) {
            th[k] = fminf(fmaxf(th[k], 0.05f), 0.5f);
            v[k] = 0.0f; isyn[k] = 0.0f;
        }
    }

    #pragma unroll 2
    for (int t = 0; t < T_STEPS; t++) {
        const int buf = t & 1;
        const bool need_cascade = (t + 1 < T_STEPS);   // i_syn dead after last step

        // ---- consume staged x_t (fetched a full step ago) ----
        cp_wait0();
        float xv[8];
        {
            float4 a = xbuf[buf * 2048 + tid];
            float4 c = xbuf[buf * 2048 + tid + 1024];
            xv[0]=a.x; xv[1]=a.y; xv[2]=a.z; xv[3]=a.w;
            xv[4]=c.x; xv[5]=c.y; xv[6]=c.z; xv[7]=c.w;
        }

        // ---- start fetching x_{t+1} into the other buffer (fire-and-forget) ----
        if (need_cascade) {
            const float4* xn = x4 + (size_t)(t + 1) * step4;
            cp_async16(&xbuf[(buf ^ 1) * 2048 + tid],        xn);
            cp_async16(&xbuf[(buf ^ 1) * 2048 + tid + 1024], xn + 1024);
            cp_commit();
        }

        // ---- LIF update + spike (refrac>0 <=> spiked at t-1 or t-2) ----
        const unsigned refr = sm1 | sm2;
        unsigned smask = 0;
        #pragma unroll
        for (int k = 0; k < 8; k++) {
            isyn[k] = fmaf(bs, isyn[k], xv[k]);
            float nv = fmaf(bm, v[k], om * isyn[k]);
            v[k] = ((refr >> k) & 1u) ? V_RESET : nv;
            if (v[k] >= th[k]) smask |= (1u << k);
        }
        sm2 = sm1; sm1 = smask;

        // ---- spike counting: pack, fold 32->16->8 lanes, u64 atomics ----
        if (need_cascade) {
            if (fast) {
                unsigned m0 = smask & 0xFu, m1 = (smask >> 4) & 0xFu;
                unsigned packed = ((m0 * 0x00204081u) & 0x01010101u)
                                + ((m1 * 0x00204081u) & 0x01010101u);
                packed += __shfl_xor_sync(0xFFFFFFFFu, packed, 16);
                unsigned other = __shfl_xor_sync(0xFFFFFFFFu, packed, 1);
                const int lane = tid & 31;
                if (lane < 16 && !(lane & 1)) {
                    // even lane m holds word m (lo) and m+1 (hi); bytes <=128, no carry
                    unsigned long long u = (unsigned long long)packed
                                         | ((unsigned long long)other << 32);
                    if (u) atomicAdd(&cnt64[buf][lane >> 1], u);
                }
            } else {
                #pragma unroll
                for (int k = 0; k < 8; k++)
                    if (smask & (1u << k)) {
                        int d = 4 * tid + (k & 3) + (k >> 2) * 4096;
                        atomicAdd(&cf_slow[buf][__ldg(&cids[d])], 1.0f);   // exact, order-free
                    }
            }
        }

        // ---- reset + streaming stores (independent of cascade result) ----
        {
            float sv[8];
            #pragma unroll
            for (int k = 0; k < 8; k++) {
                float sk = (smask >> k) & 1u ? 1.0f : 0.0f;
                sv[k] = sk;
                v[k] = fmaf(-sk, th[k], v[k]);
            }
            float4* st = s4 + (size_t)t * step4;
            float4* vt = v4 + (size_t)t * step4;
            __stcs(st,        make_float4(sv[0], sv[1], sv[2], sv[3]));
            __stcs(st + 1024, make_float4(sv[4], sv[5], sv[6], sv[7]));
            __stcs(vt,        make_float4(v[0], v[1], v[2], v[3]));
            __stcs(vt + 1024, make_float4(v[4], v[5], v[6], v[7]));
        }

        if (!need_cascade) break;      // last step: no cascade consumer

        __syncthreads();   // counts complete (barrier drains pending atomics)

        // ---- fused dot: thread (c=tid>>4, g=tid&15), shfl-reduce over g ----
        {
            const int c = tid >> 4, g = tid & 15;
            float f0, f1, f2, f3;
            if (fast) {
                unsigned u = ((const unsigned*)cnt64[buf])[g];
                f0 = __uint_as_float(__byte_perm(u, 0x4B000000u, 0x7540)) - 8388608.0f;
                f1 = __uint_as_float(__byte_perm(u, 0x4B000000u, 0x7541)) - 8388608.0f;
                f2 = __uint_as_float(__byte_perm(u, 0x4B000000u, 0x7542)) - 8388608.0f;
                f3 = __uint_as_float(__byte_perm(u, 0x4B000000u, 0x7543)) - 8388608.0f;
            } else {
                float4 cf4 = ((const float4*)cf_slow[buf])[g];
                f0 = cf4.x; f1 = cf4.y; f2 = cf4.z; f3 = cf4.w;
            }
            // W2 row strip for (c, 4g..4g+3): one conflict-free LDS.128
            float4 w = ((const float4*)W2)[tid];
            float acc = (f0 * w.x + f1 * w.y) + (f2 * w.z + f3 * w.w);
            acc += __shfl_xor_sync(0xFFFFFFFFu, acc, 1);
            acc += __shfl_xor_sync(0xFFFFFFFFu, acc, 2);
            acc += __shfl_xor_sync(0xFFFFFFFFu, acc, 4);
            acc += __shfl_xor_sync(0xFFFFFFFFu, acc, 8);
            if (g == 0) ns[c] = acc * g_sm[c];

            if (tid < 8)  cnt64[buf ^ 1][tid] = 0ull;    // consumed two syncs ago
            if (tid < NC) cf_slow[buf ^ 1][tid] = 0.0f;
        }

        __syncthreads();   // ns ready (+ next-buf zeroing ordered before next atomics)

        // ---- apply cascade to i_syn ----
        if (fast) {
            float4 nsv = ((const float4*)ns)[tid & 15];
            isyn[0] += nsv.x; isyn[1] += nsv.y; isyn[2] += nsv.z; isyn[3] += nsv.w;
            isyn[4] += nsv.x; isyn[5] += nsv.y; isyn[6] += nsv.z; isyn[7] += nsv.w;
        } else {
            #pragma unroll
            for (int k = 0; k < 8; k++) {
                int d = 4 * tid + (k & 3) + (k >> 2) * 4096;
                isyn[k] += ns[__ldg(&cids[d])];
            }
        }
    }
}

extern "C" void kernel_launch(void* const* d_in, const int* in_sizes, int n_in,
                              void* d_out, int out_size)
{
    const float* x      = (const float*)d_in[0];   // current_in [T,B,D]
    const float* th_raw = (const float*)d_in[1];   // threshold_raw [D]
    const float* bm_raw = (const float*)d_in[2];   // beta_mem_raw
    const float* bs_raw = (const float*)d_in[3];   // beta_syn_raw
    const float* nw     = (const float*)d_in[4];   // neighbor_weights [NC,NC]
    const float* gain   = (const float*)d_in[5];   // cluster_gain [NC]
    const int*   cids   = (const int*)d_in[6];     // cluster_ids [D]

    float* out_s = (float*)d_out;
    float* out_v = out_s + (size_t)T_STEPS * BATCH * DIM;

    cudaFuncSetAttribute(assoc_lif_kernel,
                         cudaFuncAttributeMaxDynamicSharedMemorySize, XBUF_BYTES);

    assoc_lif_kernel<<<BATCH, TPB, XBUF_BYTES>>>(x, th_raw, bm_raw, bs_raw, nw, gain,
                                                 cids, out_s, out_v);
}

// round 17
// speedup vs baseline: 1.1028x; 1.0903x over previous
#include <cuda_runtime.h>
#include <cuda_bf16.h>
#include <math.h>

// AssociativeLIF forward: T=8, B=128, D=8192, NC=64
// d_out = [ ss (T,B,D) | vt (T,B,D) ] float32
// One CTA per batch row. Thread owns d = 4*tid + j and d = 4096 + 4*tid + j, j=0..3.
// Fast path (cids[d] == d%64): thread's 8 neurons hit clusters 4*(tid&15)+j.
// Counts: bit->byte pack, shfl16 fold, 16x u32 smem atomics per warp.
// Cascade dot: thread (c=tid>>4, g=tid&15); W row quad held in REGISTERS.
// x input pipelined via cp.async into double-buffered smem.

#define T_STEPS 8
#define BATCH   128
#define DIM     8192
#define NC      64
#define TPB     1024
#define V_RESET (-0.1f)
#define XBUF_BYTES (2 * 2048 * 16)   // 2 buffers x 2048 float4 = 64 KB

__device__ __forceinline__ void cp_async16(void* smem_dst, const void* gmem_src) {
    unsigned s = (unsigned)__cvta_generic_to_shared(smem_dst);
    asm volatile("cp.async.cg.shared.global [%0], [%1], 16;" :: "r"(s), "l"(gmem_src) : "memory");
}
__device__ __forceinline__ void cp_commit() {
    asm volatile("cp.async.commit_group;" ::: "memory");
}
__device__ __forceinline__ void cp_wait0() {
    asm volatile("cp.async.wait_group 0;" ::: "memory");
}

__global__ __launch_bounds__(TPB, 1)
void assoc_lif_kernel(const float* __restrict__ x,        // [T,B,D]
                      const float* __restrict__ th_raw,   // [D]
                      const float* __restrict__ bm_raw,   // [1]
                      const float* __restrict__ bs_raw,   // [1]
                      const float* __restrict__ nw,       // [NC,NC]
                      const float* __restrict__ gain,     // [NC]
                      const int*   __restrict__ cids,     // [D]
                      float* __restrict__ out_s,          // [T,B,D]
                      float* __restrict__ out_v)          // [T,B,D]
{
    __shared__ float                  g_unused;           // (keeps layout simple)
    __shared__ unsigned               cnt[2][16];         // packed byte counts, double-buffered
    __shared__ __align__(16) float    cf_slow[2][NC];     // fallback float counts
    __shared__ __align__(16) float    ns[NC];
    __shared__ float bm_sh, bs_sh;
    extern __shared__ __align__(16) float4 xbuf[];        // [2][2048] staging for x

    const int b   = blockIdx.x;
    const int tid = threadIdx.x;

    const size_t bd4   = (size_t)b * DIM / 4;
    const size_t step4 = (size_t)BATCH * DIM / 4;
    const float4* x4 = (const float4*)x + bd4 + tid;

    // ---- kick off x(t=0) fetch immediately ----
    cp_async16(&xbuf[tid],        x4);
    cp_async16(&xbuf[tid + 1024], x4 + 1024);
    cp_commit();

    // ---- per-thread W row quad: w[j] = sigmoid(nw[flat 4*tid+j]) / 128 (exact scale) ----
    // Thread (c=tid>>4, g=tid&15) uses W[c][4g..4g+3] = nw flat [64c + 4g .. +3] = [4*tid ..].
    float4 wq;
    {
        float4 nq = ((const float4*)nw)[tid];
        wq.x = (1.0f / (1.0f + expf(-nq.x))) * (1.0f / 128.0f);
        wq.y = (1.0f / (1.0f + expf(-nq.y))) * (1.0f / 128.0f);
        wq.z = (1.0f / (1.0f + expf(-nq.z))) * (1.0f / 128.0f);
        wq.w = (1.0f / (1.0f + expf(-nq.w))) * (1.0f / 128.0f);
    }
    const float gn = gain[tid >> 4];        // gain for this thread's dot cluster

    if (tid < 32)      ((unsigned*)cnt)[tid] = 0u;
    if (tid < 2 * NC)  ((float*)cf_slow)[tid] = 0.0f;
    if (tid == 0) {
        float bm = 1.0f / (1.0f + expf(-bm_raw[0]));
        bm_sh = fminf(fmaxf(bm, 0.8f), 0.98f);
        bs_sh = 1.0f / (1.0f + expf(-bs_raw[0]));
        g_unused = 0.0f;
    }

    // fast path iff cids[d] == d % 64 for this thread's 8 neurons
    bool okf = true;
    #pragma unroll
    for (int j = 0; j < 4; j++) {
        okf &= (cids[4 * tid + j]        == ((4 * tid + j) & 63));
        okf &= (cids[4 * tid + 4096 + j] == ((4 * tid + j) & 63));
    }
    const bool fast = (__syncthreads_and((int)okf) != 0);   // also fences smem init

    const float bm = bm_sh, bs = bs_sh, om = 1.0f - bm;

    float4*       s4 = (float4*)out_s + bd4 + tid;
    float4*       v4 = (float4*)out_v + bd4 + tid;

    // ---- per-thread state ----
    float v[8], isyn[8], th[8];
    unsigned sm1 = 0, sm2 = 0;          // spike masks at t-1, t-2 (refractory)
    {
        const float4* t4 = (const float4*)th_raw + tid;
        float4 t0 = t4[0], t1 = t4[1024];
        th[0]=t0.x; th[1]=t0.y; th[2]=t0.z; th[3]=t0.w;
        th[4]=t1.x; th[5]=t1.y; th[6]=t1.z; th[7]=t1.w;
        #pragma unroll
        for (int k = 0; k < 8; k++) {
            th[k] = fminf(fmaxf(th[k], 0.05f), 0.5f);
            v[k] = 0.0f; isyn[k] = 0.0f;
        }
    }

    #pragma unroll 2
    for (int t = 0; t < T_STEPS; t++) {
        const int buf = t & 1;
        const bool need_cascade = (t + 1 < T_STEPS);   // i_syn dead after last step

        // ---- consume staged x_t (fetched a full step ago) ----
        cp_wait0();
        float xv[8];
        {
            float4 a = xbuf[buf * 2048 + tid];
            float4 c = xbuf[buf * 2048 + tid + 1024];
            xv[0]=a.x; xv[1]=a.y; xv[2]=a.z; xv[3]=a.w;
            xv[4]=c.x; xv[5]=c.y; xv[6]=c.z; xv[7]=c.w;
        }

        // ---- start fetching x_{t+1} into the other buffer (fire-and-forget) ----
        if (need_cascade) {
            const float4* xn = x4 + (size_t)(t + 1) * step4;
            cp_async16(&xbuf[(buf ^ 1) * 2048 + tid],        xn);
            cp_async16(&xbuf[(buf ^ 1) * 2048 + tid + 1024], xn + 1024);
            cp_commit();
        }

        // ---- LIF update + spike (refrac>0 <=> spiked at t-1 or t-2) ----
        const unsigned refr = sm1 | sm2;
        unsigned smask = 0;
        #pragma unroll
        for (int k = 0; k < 8; k++) {
            isyn[k] = fmaf(bs, isyn[k], xv[k]);
            float nv = fmaf(bm, v[k], om * isyn[k]);
            v[k] = ((refr >> k) & 1u) ? V_RESET : nv;
            if (v[k] >= th[k]) smask |= (1u << k);
        }
        sm2 = sm1; sm1 = smask;

        // ---- spike counting (16-lane u32 atomics; parallel, pre-barrier) ----
        if (need_cascade) {
            if (fast) {
                unsigned m0 = smask & 0xFu, m1 = (smask >> 4) & 0xFu;
                unsigned packed = ((m0 * 0x00204081u) & 0x01010101u)
                                + ((m1 * 0x00204081u) & 0x01010101u);
                packed += __shfl_xor_sync(0xFFFFFFFFu, packed, 16);
                if ((tid & 31) < 16 && packed)
                    atomicAdd(&cnt[buf][tid & 15], packed);   // byte c&3 of word c>>2
            } else {
                #pragma unroll
                for (int k = 0; k < 8; k++)
                    if (smask & (1u << k)) {
                        int d = 4 * tid + (k & 3) + (k >> 2) * 4096;
                        atomicAdd(&cf_slow[buf][__ldg(&cids[d])], 1.0f);   // exact, order-free
                    }
            }
        }

        // ---- reset + streaming stores (independent of cascade result) ----
        {
            float sv[8];
            #pragma unroll
            for (int k = 0; k < 8; k++) {
                float sk = (smask >> k) & 1u ? 1.0f : 0.0f;
                sv[k] = sk;
                v[k] = fmaf(-sk, th[k], v[k]);
            }
            float4* st = s4 + (size_t)t * step4;
            float4* vt = v4 + (size_t)t * step4;
            __stcs(st,        make_float4(sv[0], sv[1], sv[2], sv[3]));
            __stcs(st + 1024, make_float4(sv[4], sv[5], sv[6], sv[7]));
            __stcs(vt,        make_float4(v[0], v[1], v[2], v[3]));
            __stcs(vt + 1024, make_float4(v[4], v[5], v[6], v[7]));
        }

        if (!need_cascade) break;      // last step: no cascade consumer

        __syncthreads();   // counts complete (barrier drains pending atomics)

        // ---- fused dot: thread (c=tid>>4, g=tid&15); W quad already in registers ----
        {
            const int c = tid >> 4, g = tid & 15;
            float f0, f1, f2, f3;
            if (fast) {
                unsigned u = cnt[buf][g];
                f0 = __uint_as_float(__byte_perm(u, 0x4B000000u, 0x7540)) - 8388608.0f;
                f1 = __uint_as_float(__byte_perm(u, 0x4B000000u, 0x7541)) - 8388608.0f;
                f2 = __uint_as_float(__byte_perm(u, 0x4B000000u, 0x7542)) - 8388608.0f;
                f3 = __uint_as_float(__byte_perm(u, 0x4B000000u, 0x7543)) - 8388608.0f;
            } else {
                float4 cf4 = ((const float4*)cf_slow[buf])[g];
                f0 = cf4.x; f1 = cf4.y; f2 = cf4.z; f3 = cf4.w;
            }
            float acc = (f0 * wq.x + f1 * wq.y) + (f2 * wq.z + f3 * wq.w);
            acc += __shfl_xor_sync(0xFFFFFFFFu, acc, 1);
            acc += __shfl_xor_sync(0xFFFFFFFFu, acc, 2);
            acc += __shfl_xor_sync(0xFFFFFFFFu, acc, 4);
            acc += __shfl_xor_sync(0xFFFFFFFFu, acc, 8);
            if (g == 0) ns[c] = acc * gn;

            if (tid < 16) cnt[buf ^ 1][tid] = 0u;        // consumed two syncs ago
            if (tid < NC) cf_slow[buf ^ 1][tid] = 0.0f;
        }

        __syncthreads();   // ns ready (+ next-buf zeroing ordered before next atomics)

        // ---- apply cascade to i_syn ----
        if (fast) {
            float4 nsv = ((const float4*)ns)[tid & 15];
            isyn[0] += nsv.x; isyn[1] += nsv.y; isyn[2] += nsv.z; isyn[3] += nsv.w;
            isyn[4] += nsv.x; isyn[5] += nsv.y; isyn[6] += nsv.z; isyn[7] += nsv.w;
        } else {
            #pragma unroll
            for (int k = 0; k < 8; k++) {
                int d = 4 * tid + (k & 3) + (k >> 2) * 4096;
                isyn[k] += ns[__ldg(&cids[d])];
            }
        }
    }
}

extern "C" void kernel_launch(void* const* d_in, const int* in_sizes, int n_in,
                              void* d_out, int out_size)
{
    const float* x      = (const float*)d_in[0];   // current_in [T,B,D]
    const float* th_raw = (const float*)d_in[1];   // threshold_raw [D]
    const float* bm_raw = (const float*)d_in[2];   // beta_mem_raw
    const float* bs_raw = (const float*)d_in[3];   // beta_syn_raw
    const float* nw     = (const float*)d_in[4];   // neighbor_weights [NC,NC]
    const float* gain   = (const float*)d_in[5];   // cluster_gain [NC]
    const int*   cids   = (const int*)d_in[6];     // cluster_ids [D]

    float* out_s = (float*)d_out;
    float* out_v = out_s + (size_t)T_STEPS * BATCH * DIM;

    cudaFuncSetAttribute(assoc_lif_kernel,
                         cudaFuncAttributeMaxDynamicSharedMemorySize, XBUF_BYTES);

    assoc_lif_kernel<<<BATCH, TPB, XBUF_BYTES>>>(x, th_raw, bm_raw, bs_raw, nw, gain,
                                                 cids, out_s, out_v);
}